// round 11
// baseline (speedup 1.0000x reference)
#include <cuda_runtime.h>
#include <math.h>

// Problem dims (fixed by the reference)
#define Bsz 256
#define Tsz 512
#define Isz 64
#define Hsz 512

// Per-step partitioning: 16 batch-groups x 8 hout-groups = 128 CTAs
#define BG 16
#define JG 8
#define BT 16     // batch rows per CTA
#define JT 64     // output cols per CTA
#define NCTA (BG*JG)
#define NTHR 128

// Per-step SMEM layout (float offsets)
#define WS_OFF   0                       // W_hh slice [512][64]     = 32768 floats
#define HD_OFF   (Hsz*JT)                // h dup pairs [512][16]f2  = 16384 floats
#define SMEM_FLOATS (HD_OFF + Hsz*BT*2)
#define SMEM_BYTES  (SMEM_FLOATS * 4)    // 196,608 B -> 1 CTA/SM

// Precompute kernel SMEM
#define PWX_OFF  0                       // W_xh slice [64][64] = 4096 floats
#define PXD_OFF  (Isz*JT)                // x dup pairs [64][18]f2 = 2304 floats
#define PRE_SMEM_BYTES ((PXD_OFF + Isz*18*2) * 4)   // ~34 KB

// xh = x @ W_xh + bias, row r = b*T + t : [131072][512] fp32 = 256 MB
__device__ float g_xh[(size_t)Bsz * Tsz * Hsz];

// Hidden state, double-buffered, DUPLICATED pairs:
// [buf(2)][bg(16)][k(512)][b(16) float2]. Step t reads buf(t&1), writes buf((t&1)^1).
__device__ float g_h[2 * BG * Hsz * BT * 2];   // 2 MB

__device__ __forceinline__ void cp16(float* smem_dst, const float* gsrc) {
    unsigned d = (unsigned)__cvta_generic_to_shared(smem_dst);
    asm volatile("cp.async.cg.shared.global [%0], [%1], 16;" :: "r"(d), "l"(gsrc));
}
#define CP_COMMIT() asm volatile("cp.async.commit_group;")
#define CP_WAIT(n)  asm volatile("cp.async.wait_group %0;" :: "n"(n))

__device__ __forceinline__ void ffma2(unsigned long long& d,
                                      unsigned long long a,
                                      unsigned long long b) {
    asm("fma.rn.f32x2 %0, %1, %2, %0;" : "+l"(d) : "l"(a), "l"(b));
}
__device__ __forceinline__ unsigned long long packf2(float lo, float hi) {
    unsigned long long r;
    asm("mov.b64 %0, {%1, %2};" : "=l"(r) : "f"(lo), "f"(hi));
    return r;
}
__device__ __forceinline__ float2 unpackf2(unsigned long long v) {
    float2 r;
    asm("mov.b64 {%0, %1}, %2;" : "=f"(r.x), "=f"(r.y) : "l"(v));
    return r;
}

// ---------------------------------------------------------------------------
// Precompute: xh[r][h] = bias[h] + sum_i x[r][i] * Wxh[i][h]   (r = b*T + t)
// grid: (8192 row-tiles of 16, 8 jg), 128 threads, thread = 4 rows x 2 cols
// ---------------------------------------------------------------------------
__global__ void __launch_bounds__(NTHR)
xh_precompute_kernel(const float* __restrict__ x,
                     const float* __restrict__ Wxh,
                     const float* __restrict__ bias)
{
    __shared__ float sm[PXD_OFF + Isz*18*2];
    float*  Wxs = sm + PWX_OFF;
    float2* xd  = reinterpret_cast<float2*>(sm + PXD_OFF);

    const int tid  = threadIdx.x;
    const int rt   = blockIdx.x;          // row tile: rows rt*16 .. rt*16+15
    const int jg   = blockIdx.y;          // 0..7
    const int lane = tid & 31;
    const int wq   = tid >> 5;
    const int b0   = wq * 4;
    const int j0   = lane * 2;
    const int r0   = rt * BT;

    // W_xh slice -> smem
    #pragma unroll
    for (int m = 0; m < 8; ++m) {
        int idx = m * NTHR + tid;         // 0..1023 float4
        int k  = idx >> 4;
        int f  = idx & 15;
        *reinterpret_cast<float4*>(Wxs + k * JT + f * 4) =
            *reinterpret_cast<const float4*>(Wxh + (size_t)k * Hsz + jg * JT + f * 4);
    }
    // x tile [16][64] -> duplicated pairs xd[i][row]
    #pragma unroll
    for (int m = 0; m < 2; ++m) {
        int idx = m * NTHR + tid;         // 0..255 float4
        int bb  = idx & 15;
        int f   = idx >> 4;
        float4 v = *reinterpret_cast<const float4*>(x + (size_t)(r0 + bb) * Isz + f * 4);
        xd[(f * 4 + 0) * 18 + bb] = make_float2(v.x, v.x);
        xd[(f * 4 + 1) * 18 + bb] = make_float2(v.y, v.y);
        xd[(f * 4 + 2) * 18 + bb] = make_float2(v.z, v.z);
        xd[(f * 4 + 3) * 18 + bb] = make_float2(v.w, v.w);
    }
    const unsigned long long biasPair =
        packf2(bias[jg * JT + j0], bias[jg * JT + j0 + 1]);
    __syncthreads();

    unsigned long long acc0 = biasPair, acc1 = biasPair,
                       acc2 = biasPair, acc3 = biasPair;
    #pragma unroll 4
    for (int k = 0; k < Isz; ++k) {
        ulonglong2 xA = *reinterpret_cast<const ulonglong2*>(xd + (k * 18 + b0));
        ulonglong2 xB = *reinterpret_cast<const ulonglong2*>(xd + (k * 18 + b0 + 2));
        unsigned long long wv =
            *reinterpret_cast<const unsigned long long*>(Wxs + k * JT + j0);
        ffma2(acc0, xA.x, wv); ffma2(acc1, xA.y, wv);
        ffma2(acc2, xB.x, wv); ffma2(acc3, xB.y, wv);
    }

    float* outp = g_xh + (size_t)(r0 + b0) * Hsz + jg * JT + j0;
    *reinterpret_cast<float2*>(outp + 0 * Hsz) = unpackf2(acc0);
    *reinterpret_cast<float2*>(outp + 1 * Hsz) = unpackf2(acc1);
    *reinterpret_cast<float2*>(outp + 2 * Hsz) = unpackf2(acc2);
    *reinterpret_cast<float2*>(outp + 3 * Hsz) = unpackf2(acc3);
}

// ---------------------------------------------------------------------------
// One recurrence step: h_new = tanh(xh[:,t,:] + h @ W_hh)
// ---------------------------------------------------------------------------
#define GEMM_CHUNK(KB)                                                              \
    _Pragma("unroll 4")                                                             \
    for (int k = (KB); k < (KB) + 128; ++k) {                                       \
        ulonglong2 hA = *reinterpret_cast<const ulonglong2*>(hd + (k * BT + b0));   \
        ulonglong2 hB = *reinterpret_cast<const ulonglong2*>(hd + (k * BT + b0 + 2));\
        unsigned long long wv =                                                     \
            *reinterpret_cast<const unsigned long long*>(Ws + k * JT + j0);         \
        ffma2(acc0, hA.x, wv); ffma2(acc1, hA.y, wv);                               \
        ffma2(acc2, hB.x, wv); ffma2(acc3, hB.y, wv);                               \
    }

__global__ void __launch_bounds__(NTHR, 1)
rnn_step_kernel(const float* __restrict__ Whh, int t)
{
    extern __shared__ float sm[];
    float*  Ws = sm + WS_OFF;
    float2* hd = reinterpret_cast<float2*>(sm + HD_OFF);

    const int tid  = threadIdx.x;
    const int bg   = blockIdx.x >> 3;   // 0..15
    const int jg   = blockIdx.x & 7;    // 0..7
    const int lane = tid & 31;
    const int wq   = tid >> 5;
    const int b0   = wq * 4;            // 4 batch rows per thread (warp-uniform)
    const int j0   = lane * 2;          // 2 output cols per thread

    // ---- Stream h (dup pairs) + W_hh slice in 4 interleaved commit-groups ----
    if (t > 0) {
        const float* hg = g_h + (size_t)((t & 1) * BG + bg) * (Hsz * BT * 2);
        #pragma unroll
        for (int c = 0; c < 4; ++c) {
            #pragma unroll
            for (int m = 0; m < 8; ++m) {                 // h chunk: 1024 float4
                int idx = c * 1024 + m * NTHR + tid;
                cp16(reinterpret_cast<float*>(hd) + idx * 4, hg + idx * 4);
            }
            #pragma unroll
            for (int m = 0; m < 16; ++m) {                // W chunk: 2048 float4
                int i2 = c * 2048 + m * NTHR + tid;
                int k  = i2 >> 4;
                int f  = i2 & 15;
                cp16(Ws + k * JT + f * 4,
                     Whh + (size_t)k * Hsz + jg * JT + f * 4);
            }
            CP_COMMIT();
        }
    }

    // ---- acc init = xh (bias already folded in) ----
    const float* xhp = g_xh + ((size_t)(bg * BT + b0) * Tsz + t) * Hsz + jg * JT + j0;
    float2 xi0 = __ldg(reinterpret_cast<const float2*>(xhp + 0 * (size_t)Tsz * Hsz));
    float2 xi1 = __ldg(reinterpret_cast<const float2*>(xhp + 1 * (size_t)Tsz * Hsz));
    float2 xi2 = __ldg(reinterpret_cast<const float2*>(xhp + 2 * (size_t)Tsz * Hsz));
    float2 xi3 = __ldg(reinterpret_cast<const float2*>(xhp + 3 * (size_t)Tsz * Hsz));
    unsigned long long acc0 = packf2(xi0.x, xi0.y);
    unsigned long long acc1 = packf2(xi1.x, xi1.y);
    unsigned long long acc2 = packf2(xi2.x, xi2.y);
    unsigned long long acc3 = packf2(xi3.x, xi3.y);

    if (t > 0) {
        // chunk-pipelined recurrent GEMM
        CP_WAIT(3); __syncthreads(); GEMM_CHUNK(0);
        CP_WAIT(2); __syncthreads(); GEMM_CHUNK(128);
        CP_WAIT(1); __syncthreads(); GEMM_CHUNK(256);
        CP_WAIT(0); __syncthreads(); GEMM_CHUNK(384);
    }

    // ---- Epilogue: tanh + store duplicated pairs to write buffer ----
    float2 a0 = unpackf2(acc0), a1 = unpackf2(acc1),
           a2 = unpackf2(acc2), a3 = unpackf2(acc3);
    float t00 = tanhf(a0.x), t01 = tanhf(a0.y);
    float t10 = tanhf(a1.x), t11 = tanhf(a1.y);
    float t20 = tanhf(a2.x), t21 = tanhf(a2.y);
    float t30 = tanhf(a3.x), t31 = tanhf(a3.y);

    float* hw = g_h + (size_t)(((t & 1) ^ 1) * BG + bg) * (Hsz * BT * 2);
    const int kg0 = jg * JT + j0;
    float4* p0 = reinterpret_cast<float4*>(hw + (size_t)(kg0 * BT + b0) * 2);
    p0[0] = make_float4(t00, t00, t10, t10);
    p0[1] = make_float4(t20, t20, t30, t30);
    float4* p1 = reinterpret_cast<float4*>(hw + (size_t)((kg0 + 1) * BT + b0) * 2);
    p1[0] = make_float4(t01, t01, t11, t11);
    p1[1] = make_float4(t21, t21, t31, t31);
}

// out[b] = fc_b + sum_j fc_w[j] * h_final[b][j]; final h (t=511) is buf 0 (pairs)
__global__ void rnn_fc_kernel(const float* __restrict__ fcw,
                              const float* __restrict__ fcb,
                              float* __restrict__ out)
{
    int b    = blockIdx.x;       // 0..255
    int bg   = b >> 4;
    int bl   = b & 15;
    int lane = threadIdx.x;      // 32 threads

    const float2* hg = reinterpret_cast<const float2*>(g_h)
                     + (size_t)bg * (Hsz * BT);   // buffer 0
    float s = 0.f;
    #pragma unroll 4
    for (int j = lane; j < Hsz; j += 32)
        s += fcw[j] * hg[(size_t)j * BT + bl].x;
    #pragma unroll
    for (int o = 16; o; o >>= 1) s += __shfl_down_sync(0xffffffffu, s, o);
    if (lane == 0) out[b] = s + fcb[0];
}

extern "C" void kernel_launch(void* const* d_in, const int* in_sizes, int n_in,
                              void* d_out, int out_size)
{
    const float* x    = (const float*)d_in[0];   // (256, 512, 64)
    const float* Wxh  = (const float*)d_in[1];   // (64, 512)
    const float* Whh  = (const float*)d_in[2];   // (512, 512)
    const float* bias = (const float*)d_in[3];   // (512,)
    const float* fcw  = (const float*)d_in[4];   // (1, 512)
    const float* fcb  = (const float*)d_in[5];   // (1,)
    float* out = (float*)d_out;                  // (256, 1) fp32

    cudaFuncSetAttribute(rnn_step_kernel,
                         cudaFuncAttributeMaxDynamicSharedMemorySize, SMEM_BYTES);

    dim3 pre_grid(Bsz * Tsz / BT, JG);           // 8192 x 8
    xh_precompute_kernel<<<pre_grid, NTHR>>>(x, Wxh, bias);

    for (int t = 0; t < Tsz; ++t)
        rnn_step_kernel<<<NCTA, NTHR, SMEM_BYTES>>>(Whh, t);

    rnn_fc_kernel<<<Bsz, 32>>>(fcw, fcb, out);
}

// round 14
// speedup vs baseline: 1.6407x; 1.6407x over previous
#include <cuda_runtime.h>
#include <math.h>

// Problem dims (fixed by the reference)
#define Bsz 256
#define Tsz 512
#define Isz 64
#define Hsz 512

// Step-kernel partitioning: 8 batch-groups (32 rows) x 8 hout-groups (64 cols)
#define BG 8
#define JG 8
#define BT 32
#define JT 64
#define NCTA (BG*JG)   // 64
#define NTHR 256       // 8 warps; warp w = n-tile w (8 cols), both m-tiles

#define NKT (Hsz/8)    // 64 k-tiles of 8
#define HD_U4   (NKT*2*32)          // h A-fragments: [kt][mt][lane] uint4 = 64 KB
#define STG_U32 (8*2*16*8)          // epilogue transpose staging: 8 KB
#define SMEM_BYTES (HD_U4*16 + STG_U32*4)   // 73,728 B

// Precompute kernel SMEM (FFMA2 xh path, carried from the working R9 kernel)
#define PWX_OFF  0
#define PXD_OFF  (Isz*JT)

// ---- Global scratch ----
// xh = x @ W_xh + bias : [B*T][H] fp32 (row r = b*T + t)
__device__ float g_xh[(size_t)Bsz * Tsz * Hsz];
// W_hh in B-fragment order, tf32 bits: [nt(64)][kt(64)][lane(32)][2]
__device__ unsigned g_w[64 * 64 * 32 * 2];
// h in A-fragment order (tf32 bits), double buffered:
// [buf][bg][kt(64)][mt(2)][lane(32)] uint4. Step t reads buf(t&1), writes buf((t&1)^1).
__device__ uint4 g_hfrag[2 * BG * NKT * 2 * 32];
// Full-precision final hidden state for the FC epilogue
__device__ float g_hfin[Bsz * Hsz];

// ---- helpers ----
__device__ __forceinline__ void cp16(void* smem_dst, const void* gsrc) {
    unsigned d = (unsigned)__cvta_generic_to_shared(smem_dst);
    asm volatile("cp.async.cg.shared.global [%0], [%1], 16;" :: "r"(d), "l"(gsrc));
}
#define CP_COMMIT() asm volatile("cp.async.commit_group;")
#define CP_WAIT(n)  asm volatile("cp.async.wait_group %0;" :: "n"(n))

__device__ __forceinline__ unsigned f2tf32(float f) {
    unsigned r;
    asm("cvt.rna.tf32.f32 %0, %1;" : "=r"(r) : "f"(f));
    return r;
}
__device__ __forceinline__ void mma_tf32(float& d0, float& d1, float& d2, float& d3,
                                         uint4 a, uint2 b) {
    asm volatile(
        "mma.sync.aligned.m16n8k8.row.col.f32.tf32.tf32.f32 "
        "{%0,%1,%2,%3}, {%4,%5,%6,%7}, {%8,%9}, {%0,%1,%2,%3};"
        : "+f"(d0), "+f"(d1), "+f"(d2), "+f"(d3)
        : "r"(a.x), "r"(a.y), "r"(a.z), "r"(a.w), "r"(b.x), "r"(b.y));
}
__device__ __forceinline__ void ffma2(unsigned long long& d,
                                      unsigned long long a, unsigned long long b) {
    asm("fma.rn.f32x2 %0, %1, %2, %0;" : "+l"(d) : "l"(a), "l"(b));
}
__device__ __forceinline__ unsigned long long packf2(float lo, float hi) {
    unsigned long long r;
    asm("mov.b64 %0, {%1, %2};" : "=l"(r) : "f"(lo), "f"(hi));
    return r;
}
__device__ __forceinline__ float2 unpackf2(unsigned long long v) {
    float2 r;
    asm("mov.b64 {%0, %1}, %2;" : "=f"(r.x), "=f"(r.y) : "l"(v));
    return r;
}

// ---------------------------------------------------------------------------
// One-time: linearize W_hh into B-fragment order (tf32).
// b0 = Whh[kt*8+tig][nt*8+gid], b1 = Whh[kt*8+tig+4][nt*8+gid]
// ---------------------------------------------------------------------------
__global__ void wlin_setup_kernel(const float* __restrict__ Whh) {
    int idx = blockIdx.x * 256 + threadIdx.x;      // 0 .. 131071 = nt*2048 + kt*32 + lane
    int nt   = idx >> 11;
    int kt   = (idx >> 5) & 63;
    int lane = idx & 31;
    int gid  = lane >> 2, tig = lane & 3;
    int col  = nt * 8 + gid;
    g_w[idx * 2 + 0] = f2tf32(Whh[(size_t)(kt * 8 + tig)     * Hsz + col]);
    g_w[idx * 2 + 1] = f2tf32(Whh[(size_t)(kt * 8 + tig + 4) * Hsz + col]);
}

// ---------------------------------------------------------------------------
// Precompute xh[r][h] = bias[h] + sum_i x[r][i]*Wxh[i][h]  (verbatim from R9 — worked)
// ---------------------------------------------------------------------------
__global__ void __launch_bounds__(128)
xh_precompute_kernel(const float* __restrict__ x,
                     const float* __restrict__ Wxh,
                     const float* __restrict__ bias)
{
    __shared__ float sm[PXD_OFF + Isz*18*2];
    float*  Wxs = sm + PWX_OFF;
    float2* xd  = reinterpret_cast<float2*>(sm + PXD_OFF);

    const int tid  = threadIdx.x;
    const int rt   = blockIdx.x;
    const int jg   = blockIdx.y;
    const int lane = tid & 31;
    const int wq   = tid >> 5;
    const int b0   = wq * 4;
    const int j0   = lane * 2;
    const int r0   = rt * 16;

    #pragma unroll
    for (int m = 0; m < 8; ++m) {
        int idx = m * 128 + tid;
        int k  = idx >> 4;
        int f  = idx & 15;
        *reinterpret_cast<float4*>(Wxs + k * JT + f * 4) =
            *reinterpret_cast<const float4*>(Wxh + (size_t)k * Hsz + jg * JT + f * 4);
    }
    #pragma unroll
    for (int m = 0; m < 2; ++m) {
        int idx = m * 128 + tid;
        int bb  = idx & 15;
        int f   = idx >> 4;
        float4 v = *reinterpret_cast<const float4*>(x + (size_t)(r0 + bb) * Isz + f * 4);
        xd[(f * 4 + 0) * 18 + bb] = make_float2(v.x, v.x);
        xd[(f * 4 + 1) * 18 + bb] = make_float2(v.y, v.y);
        xd[(f * 4 + 2) * 18 + bb] = make_float2(v.z, v.z);
        xd[(f * 4 + 3) * 18 + bb] = make_float2(v.w, v.w);
    }
    const unsigned long long biasPair =
        packf2(bias[jg * JT + j0], bias[jg * JT + j0 + 1]);
    __syncthreads();

    unsigned long long acc0 = biasPair, acc1 = biasPair,
                       acc2 = biasPair, acc3 = biasPair;
    #pragma unroll 4
    for (int k = 0; k < Isz; ++k) {
        ulonglong2 xA = *reinterpret_cast<const ulonglong2*>(xd + (k * 18 + b0));
        ulonglong2 xB = *reinterpret_cast<const ulonglong2*>(xd + (k * 18 + b0 + 2));
        unsigned long long wv =
            *reinterpret_cast<const unsigned long long*>(Wxs + k * JT + j0);
        ffma2(acc0, xA.x, wv); ffma2(acc1, xA.y, wv);
        ffma2(acc2, xB.x, wv); ffma2(acc3, xB.y, wv);
    }

    float* outp = g_xh + (size_t)(r0 + b0) * Hsz + jg * JT + j0;
    *reinterpret_cast<float2*>(outp + 0 * Hsz) = unpackf2(acc0);
    *reinterpret_cast<float2*>(outp + 1 * Hsz) = unpackf2(acc1);
    *reinterpret_cast<float2*>(outp + 2 * Hsz) = unpackf2(acc2);
    *reinterpret_cast<float2*>(outp + 3 * Hsz) = unpackf2(acc3);
}

// ---------------------------------------------------------------------------
// One recurrence step on tensor cores: h_new = tanh(xh[:,t,:] + h @ W_hh)
// ---------------------------------------------------------------------------
__global__ void __launch_bounds__(NTHR, 1)
rnn_step_kernel(int t)
{
    extern __shared__ uint4 smem4[];
    uint4*    hd  = smem4;                                   // A fragments
    unsigned* stg = reinterpret_cast<unsigned*>(smem4 + HD_U4);

    const int tid  = threadIdx.x;
    const int wid  = tid >> 5;          // n-tile within CTA (0..7)
    const int lane = tid & 31;
    const int gid  = lane >> 2;
    const int tig  = lane & 3;
    const int bg   = blockIdx.x >> 3;   // 0..7
    const int jg   = blockIdx.x & 7;    // 0..7
    const int ntg  = jg * 8 + wid;      // global n-tile 0..63

    // ---- Stage this bg's A fragments (h from step t-1), 4 cp.async chunks ----
    if (t > 0) {
        const uint4* hg = g_hfrag + ((size_t)(t & 1) * BG + bg) * (NKT * 2 * 32);
        #pragma unroll
        for (int c = 0; c < 4; ++c) {
            #pragma unroll
            for (int m = 0; m < 4; ++m) {
                int idx = c * 1024 + m * NTHR + tid;
                cp16(hd + idx, hg + idx);
            }
            CP_COMMIT();
        }
    }

    // ---- xh C-fragment loads (issued early; consumed in the epilogue) ----
    const int r0 = bg * 32 + gid;               // mt0 rows: r0, r0+8; mt1: +16, +24
    const int j0 = jg * 64 + wid * 8 + 2 * tig;
    const size_t TH = (size_t)Tsz * Hsz;
    const float* xb = g_xh + (size_t)t * Hsz + j0;
    float2 x00 = __ldg(reinterpret_cast<const float2*>(xb + (size_t)(r0     ) * TH));
    float2 x01 = __ldg(reinterpret_cast<const float2*>(xb + (size_t)(r0 +  8) * TH));
    float2 x10 = __ldg(reinterpret_cast<const float2*>(xb + (size_t)(r0 + 16) * TH));
    float2 x11 = __ldg(reinterpret_cast<const float2*>(xb + (size_t)(r0 + 24) * TH));

    float c00 = 0.f, c01 = 0.f, c02 = 0.f, c03 = 0.f;   // mt0 accum
    float c10 = 0.f, c11 = 0.f, c12 = 0.f, c13 = 0.f;   // mt1 accum

    if (t > 0) {
        const uint2* wl = reinterpret_cast<const uint2*>(g_w)
                        + (size_t)ntg * (NKT * 32) + lane;
        #pragma unroll
        for (int c = 0; c < 4; ++c) {
            if (c == 0) { CP_WAIT(3); } else if (c == 1) { CP_WAIT(2); }
            else if (c == 2) { CP_WAIT(1); } else { CP_WAIT(0); }
            __syncthreads();
            #pragma unroll 8
            for (int kt = c * 16; kt < c * 16 + 16; ++kt) {
                uint4 a0 = hd[(kt * 2 + 0) * 32 + lane];
                uint4 a1 = hd[(kt * 2 + 1) * 32 + lane];
                uint2 bv = __ldg(wl + kt * 32);
                mma_tf32(c00, c01, c02, c03, a0, bv);
                mma_tf32(c10, c11, c12, c13, a1, bv);
            }
        }
    }

    // ---- Epilogue: add xh, tanh ----
    float v00 = tanhf(c00 + x00.x), v01 = tanhf(c01 + x00.y);   // (r0,    j0/j0+1)
    float v02 = tanhf(c02 + x01.x), v03 = tanhf(c03 + x01.y);   // (r0+8,  ..)
    float v10 = tanhf(c10 + x10.x), v11 = tanhf(c11 + x10.y);   // (r0+16, ..)
    float v12 = tanhf(c12 + x11.x), v13 = tanhf(c13 + x11.y);   // (r0+24, ..)

    if (t == Tsz - 1) {   // full-precision final h for the FC
        float* hf = g_hfin + j0;
        *reinterpret_cast<float2*>(hf + (size_t)(r0     ) * Hsz) = make_float2(v00, v01);
        *reinterpret_cast<float2*>(hf + (size_t)(r0 +  8) * Hsz) = make_float2(v02, v03);
        *reinterpret_cast<float2*>(hf + (size_t)(r0 + 16) * Hsz) = make_float2(v10, v11);
        *reinterpret_cast<float2*>(hf + (size_t)(r0 + 24) * Hsz) = make_float2(v12, v13);
    }

    // ---- C-layout -> A-layout transpose via per-warp staging, then store ----
    const int wo = wid * 256;          // [mt][row16][col8] u32
    stg[wo +   0 + gid * 8 + 2 * tig    ] = f2tf32(v00);
    stg[wo +   0 + gid * 8 + 2 * tig + 1] = f2tf32(v01);
    stg[wo +   0 + (gid + 8) * 8 + 2 * tig    ] = f2tf32(v02);
    stg[wo +   0 + (gid + 8) * 8 + 2 * tig + 1] = f2tf32(v03);
    stg[wo + 128 + gid * 8 + 2 * tig    ] = f2tf32(v10);
    stg[wo + 128 + gid * 8 + 2 * tig + 1] = f2tf32(v11);
    stg[wo + 128 + (gid + 8) * 8 + 2 * tig    ] = f2tf32(v12);
    stg[wo + 128 + (gid + 8) * 8 + 2 * tig + 1] = f2tf32(v13);
    __syncwarp();

    uint4* hw = g_hfrag + ((size_t)((t & 1) ^ 1) * BG + bg) * (NKT * 2 * 32);
    const int ktw = jg * 8 + wid;      // this warp produced k-tile ktw
    #pragma unroll
    for (int mt = 0; mt < 2; ++mt) {
        uint4 a;
        a.x = stg[wo + mt * 128 + gid * 8 + tig];
        a.y = stg[wo + mt * 128 + (gid + 8) * 8 + tig];
        a.z = stg[wo + mt * 128 + gid * 8 + tig + 4];
        a.w = stg[wo + mt * 128 + (gid + 8) * 8 + tig + 4];
        hw[(ktw * 2 + mt) * 32 + lane] = a;
    }
}

// out[b] = fc_b + sum_j fc_w[j] * h_final[b][j]
__global__ void rnn_fc_kernel(const float* __restrict__ fcw,
                              const float* __restrict__ fcb,
                              float* __restrict__ out)
{
    int b    = blockIdx.x;       // 0..255
    int lane = threadIdx.x;      // 32 threads
    const float* hb = g_hfin + (size_t)b * Hsz;
    float s = 0.f;
    #pragma unroll 4
    for (int j = lane; j < Hsz; j += 32)
        s += fcw[j] * hb[j];
    #pragma unroll
    for (int o = 16; o; o >>= 1) s += __shfl_down_sync(0xffffffffu, s, o);
    if (lane == 0) out[b] = s + fcb[0];
}

extern "C" void kernel_launch(void* const* d_in, const int* in_sizes, int n_in,
                              void* d_out, int out_size)
{
    const float* x    = (const float*)d_in[0];   // (256, 512, 64)
    const float* Wxh  = (const float*)d_in[1];   // (64, 512)
    const float* Whh  = (const float*)d_in[2];   // (512, 512)
    const float* bias = (const float*)d_in[3];   // (512,)
    const float* fcw  = (const float*)d_in[4];   // (1, 512)
    const float* fcb  = (const float*)d_in[5];   // (1,)
    float* out = (float*)d_out;                  // (256, 1) fp32

    cudaFuncSetAttribute(rnn_step_kernel,
                         cudaFuncAttributeMaxDynamicSharedMemorySize, SMEM_BYTES);

    wlin_setup_kernel<<<512, 256>>>(Whh);
    dim3 pre_grid(Bsz * Tsz / 16, JG);           // 8192 x 8
    xh_precompute_kernel<<<pre_grid, 128>>>(x, Wxh, bias);

    for (int t = 0; t < Tsz; ++t)
        rnn_step_kernel<<<NCTA, NTHR, SMEM_BYTES>>>(t);

    rnn_fc_kernel<<<Bsz, 32>>>(fcw, fcb, out);
}

// round 15
// speedup vs baseline: 2.2089x; 1.3463x over previous
#include <cuda_runtime.h>
#include <math.h>

// Problem dims (fixed by the reference)
#define Bsz 256
#define Tsz 512
#define Isz 64
#define Hsz 512

// Persistent partitioning: 8 batch-groups (32 rows) x 8 hout-groups (64 cols)
#define BG 8
#define JG 8
#define NCTA (BG*JG)   // 64 CTAs, 1/SM, all wave-1 resident
#define NTHR 128       // 4 warps; warp w covers m-tiles{0,1} x n-tiles{2w,2w+1}

#define NKT (Hsz/8)    // 64 k-tiles

// SMEM layout (bytes)
#define WSM_U2   (8*NKT*32)         // W slice  [ln(8)][kt(64)][lane] uint2 = 128 KB
#define HD_U4    (NKT*2*32)         // h A-frags [kt][mt][lane] uint4       = 64 KB
#define STG_U32  (4*512)            // transpose staging [warp][512]        = 8 KB
#define SMEM_BYTES (WSM_U2*8 + HD_U4*16 + STG_U32*4)   // 200,704 B

// Precompute kernel SMEM
#define PWX_OFF  0
#define PXD_OFF  (Isz*64)

// ---- Global scratch ----
__device__ float    g_xh[(size_t)Bsz * Tsz * Hsz];        // x@Wxh + bias
__device__ unsigned g_w[64 * 64 * 32 * 2];                // W_hh B-frag order (tf32)
__device__ uint4    g_hfrag[2 * BG * NKT * 2 * 32];       // h A-frags, double buffered
__device__ float    g_hfin[Bsz * Hsz];                    // fp32 final h
__device__ unsigned g_cnt[BG];

// ---- helpers ----
__device__ __forceinline__ void cp16(void* smem_dst, const void* gsrc) {
    unsigned d = (unsigned)__cvta_generic_to_shared(smem_dst);
    asm volatile("cp.async.cg.shared.global [%0], [%1], 16;" :: "r"(d), "l"(gsrc));
}
#define CP_COMMIT() asm volatile("cp.async.commit_group;")
#define CP_WAIT(n)  asm volatile("cp.async.wait_group %0;" :: "n"(n))

__device__ __forceinline__ unsigned f2tf32(float f) {
    unsigned r;
    asm("cvt.rna.tf32.f32 %0, %1;" : "=r"(r) : "f"(f));
    return r;
}
__device__ __forceinline__ void mma_tf32(float& d0, float& d1, float& d2, float& d3,
                                         uint4 a, uint2 b) {
    asm volatile(
        "mma.sync.aligned.m16n8k8.row.col.f32.tf32.tf32.f32 "
        "{%0,%1,%2,%3}, {%4,%5,%6,%7}, {%8,%9}, {%0,%1,%2,%3};"
        : "+f"(d0), "+f"(d1), "+f"(d2), "+f"(d3)
        : "r"(a.x), "r"(a.y), "r"(a.z), "r"(a.w), "r"(b.x), "r"(b.y));
}
__device__ __forceinline__ void ffma2(unsigned long long& d,
                                      unsigned long long a, unsigned long long b) {
    asm("fma.rn.f32x2 %0, %1, %2, %0;" : "+l"(d) : "l"(a), "l"(b));
}
__device__ __forceinline__ unsigned long long packf2(float lo, float hi) {
    unsigned long long r;
    asm("mov.b64 %0, {%1, %2};" : "=l"(r) : "f"(lo), "f"(hi));
    return r;
}
__device__ __forceinline__ float2 unpackf2(unsigned long long v) {
    float2 r;
    asm("mov.b64 {%0, %1}, %2;" : "=f"(r.x), "=f"(r.y) : "l"(v));
    return r;
}

// ---------------------------------------------------------------------------
// One-time: W_hh -> B-fragment order (tf32). [nt][kt][lane][2]; contiguous per jg.
// ---------------------------------------------------------------------------
__global__ void wlin_setup_kernel(const float* __restrict__ Whh) {
    int idx = blockIdx.x * 256 + threadIdx.x;      // nt*2048 + kt*32 + lane
    int nt   = idx >> 11;
    int kt   = (idx >> 5) & 63;
    int lane = idx & 31;
    int gid  = lane >> 2, tig = lane & 3;
    int col  = nt * 8 + gid;
    g_w[idx * 2 + 0] = f2tf32(Whh[(size_t)(kt * 8 + tig)     * Hsz + col]);
    g_w[idx * 2 + 1] = f2tf32(Whh[(size_t)(kt * 8 + tig + 4) * Hsz + col]);
}

__global__ void cnt_init_kernel() {
    if (threadIdx.x < BG) g_cnt[threadIdx.x] = 0u;
}

// ---------------------------------------------------------------------------
// Precompute xh[r][h] = bias[h] + sum_i x[r][i]*Wxh[i][h]   (r = b*T + t)
// ---------------------------------------------------------------------------
__global__ void __launch_bounds__(128)
xh_precompute_kernel(const float* __restrict__ x,
                     const float* __restrict__ Wxh,
                     const float* __restrict__ bias)
{
    __shared__ float sm[PXD_OFF + Isz*18*2];
    float*  Wxs = sm + PWX_OFF;
    float2* xd  = reinterpret_cast<float2*>(sm + PXD_OFF);

    const int tid  = threadIdx.x;
    const int rt   = blockIdx.x;
    const int jg   = blockIdx.y;
    const int lane = tid & 31;
    const int wq   = tid >> 5;
    const int b0   = wq * 4;
    const int j0   = lane * 2;
    const int r0   = rt * 16;

    #pragma unroll
    for (int m = 0; m < 8; ++m) {
        int idx = m * 128 + tid;
        int k  = idx >> 4;
        int f  = idx & 15;
        *reinterpret_cast<float4*>(Wxs + k * 64 + f * 4) =
            *reinterpret_cast<const float4*>(Wxh + (size_t)k * Hsz + jg * 64 + f * 4);
    }
    #pragma unroll
    for (int m = 0; m < 2; ++m) {
        int idx = m * 128 + tid;
        int bb  = idx & 15;
        int f   = idx >> 4;
        float4 v = *reinterpret_cast<const float4*>(x + (size_t)(r0 + bb) * Isz + f * 4);
        xd[(f * 4 + 0) * 18 + bb] = make_float2(v.x, v.x);
        xd[(f * 4 + 1) * 18 + bb] = make_float2(v.y, v.y);
        xd[(f * 4 + 2) * 18 + bb] = make_float2(v.z, v.z);
        xd[(f * 4 + 3) * 18 + bb] = make_float2(v.w, v.w);
    }
    const unsigned long long biasPair =
        packf2(bias[jg * 64 + j0], bias[jg * 64 + j0 + 1]);
    __syncthreads();

    unsigned long long acc0 = biasPair, acc1 = biasPair,
                       acc2 = biasPair, acc3 = biasPair;
    #pragma unroll 4
    for (int k = 0; k < Isz; ++k) {
        ulonglong2 xA = *reinterpret_cast<const ulonglong2*>(xd + (k * 18 + b0));
        ulonglong2 xB = *reinterpret_cast<const ulonglong2*>(xd + (k * 18 + b0 + 2));
        unsigned long long wv =
            *reinterpret_cast<const unsigned long long*>(Wxs + k * 64 + j0);
        ffma2(acc0, xA.x, wv); ffma2(acc1, xA.y, wv);
        ffma2(acc2, xB.x, wv); ffma2(acc3, xB.y, wv);
    }

    float* outp = g_xh + (size_t)(r0 + b0) * Hsz + jg * 64 + j0;
    *reinterpret_cast<float2*>(outp + 0 * Hsz) = unpackf2(acc0);
    *reinterpret_cast<float2*>(outp + 1 * Hsz) = unpackf2(acc1);
    *reinterpret_cast<float2*>(outp + 2 * Hsz) = unpackf2(acc2);
    *reinterpret_cast<float2*>(outp + 3 * Hsz) = unpackf2(acc3);
}

// ---------------------------------------------------------------------------
// Persistent recurrence: 512 steps, W SMEM-resident, per-bg counter sync.
// ---------------------------------------------------------------------------
__global__ void __launch_bounds__(NTHR, 1)
rnn_persist_kernel()
{
    extern __shared__ unsigned smu[];
    uint2*    wsm = reinterpret_cast<uint2*>(smu);                  // [ln][kt][lane]
    uint4*    hd  = reinterpret_cast<uint4*>(smu + WSM_U2*2);       // [kt][mt][lane]
    unsigned* stg = smu + WSM_U2*2 + HD_U4*4;                       // [warp][512]

    const int tid  = threadIdx.x;
    const int wid  = tid >> 5;          // 0..3
    const int lane = tid & 31;
    const int gid  = lane >> 2;
    const int tig  = lane & 3;
    const int bg   = blockIdx.x >> 3;   // 0..7
    const int jg   = blockIdx.x & 7;    // 0..7

    // ---- One-time: W slice for this jg (contiguous 128 KB) -> SMEM ----
    {
        const uint4* wg = reinterpret_cast<const uint4*>(g_w) + (size_t)jg * (WSM_U2 / 2);
        #pragma unroll 8
        for (int m = 0; m < (WSM_U2 / 2) / NTHR; ++m)               // 64 iters
            reinterpret_cast<uint4*>(wsm)[m * NTHR + tid] = wg[m * NTHR + tid];
    }
    __syncthreads();

    const int r0 = bg * 32 + gid;                 // rows r0, r0+8 (mt0); +16,+24 (mt1)
    const size_t TH = (size_t)Tsz * Hsz;
    const int jcA = jg * 64 + (2*wid    ) * 8 + 2 * tig;
    const int jcB = jg * 64 + (2*wid + 1) * 8 + 2 * tig;
    const int wo  = wid * 512;

    for (int t = 0; t < Tsz; ++t) {
        // ---- xh prefetch (independent of h; hides spin + DRAM latency) ----
        const float* xbA = g_xh + (size_t)t * Hsz + jcA;
        const float* xbB = g_xh + (size_t)t * Hsz + jcB;
        float2 xA00 = __ldg(reinterpret_cast<const float2*>(xbA + (size_t)(r0     ) * TH));
        float2 xA01 = __ldg(reinterpret_cast<const float2*>(xbA + (size_t)(r0 +  8) * TH));
        float2 xA10 = __ldg(reinterpret_cast<const float2*>(xbA + (size_t)(r0 + 16) * TH));
        float2 xA11 = __ldg(reinterpret_cast<const float2*>(xbA + (size_t)(r0 + 24) * TH));
        float2 xB00 = __ldg(reinterpret_cast<const float2*>(xbB + (size_t)(r0     ) * TH));
        float2 xB01 = __ldg(reinterpret_cast<const float2*>(xbB + (size_t)(r0 +  8) * TH));
        float2 xB10 = __ldg(reinterpret_cast<const float2*>(xbB + (size_t)(r0 + 16) * TH));
        float2 xB11 = __ldg(reinterpret_cast<const float2*>(xbB + (size_t)(r0 + 24) * TH));

        // C accum: [ntile A/B][mt][4]
        float cA00=0, cA01=0, cA02=0, cA03=0, cA10=0, cA11=0, cA12=0, cA13=0;
        float cB00=0, cB01=0, cB02=0, cB03=0, cB10=0, cB11=0, cB12=0, cB13=0;

        if (t > 0) {
            // ---- Acquire: all 8 producers of this bg finished step t-1 ----
            if (tid == 0) {
                volatile unsigned* c = &g_cnt[bg];
                const unsigned target = 8u * (unsigned)t;
                while (*c < target) { __nanosleep(32); }
            }
            __syncthreads();
            __threadfence();   // order subsequent reads after the observed release

            // ---- Stream h A-frags (64 KB) in 4 cp.async chunks ----
            const uint4* hg = g_hfrag + ((size_t)(t & 1) * BG + bg) * (NKT * 2 * 32);
            #pragma unroll
            for (int c = 0; c < 4; ++c) {
                #pragma unroll
                for (int m = 0; m < 8; ++m) {
                    int idx = c * 1024 + m * NTHR + tid;
                    cp16(hd + idx, hg + idx);
                }
                CP_COMMIT();
            }

            const uint2* wA = wsm + (size_t)(2*wid    ) * (NKT * 32) + lane;
            const uint2* wB = wsm + (size_t)(2*wid + 1) * (NKT * 32) + lane;
            #pragma unroll
            for (int c = 0; c < 4; ++c) {
                if      (c == 0) { CP_WAIT(3); }
                else if (c == 1) { CP_WAIT(2); }
                else if (c == 2) { CP_WAIT(1); }
                else             { CP_WAIT(0); }
                __syncthreads();
                #pragma unroll 8
                for (int kt = c * 16; kt < c * 16 + 16; ++kt) {
                    uint4 a0 = hd[(kt * 2 + 0) * 32 + lane];
                    uint4 a1 = hd[(kt * 2 + 1) * 32 + lane];
                    uint2 b0 = wA[kt * 32];
                    uint2 b1 = wB[kt * 32];
                    mma_tf32(cA00, cA01, cA02, cA03, a0, b0);
                    mma_tf32(cA10, cA11, cA12, cA13, a1, b0);
                    mma_tf32(cB00, cB01, cB02, cB03, a0, b1);
                    mma_tf32(cB10, cB11, cB12, cB13, a1, b1);
                }
            }
        }

        // ---- Epilogue: add xh, tanh ----
        float vA00 = tanhf(cA00 + xA00.x), vA01 = tanhf(cA01 + xA00.y);
        float vA02 = tanhf(cA02 + xA01.x), vA03 = tanhf(cA03 + xA01.y);
        float vA10 = tanhf(cA10 + xA10.x), vA11 = tanhf(cA11 + xA10.y);
        float vA12 = tanhf(cA12 + xA11.x), vA13 = tanhf(cA13 + xA11.y);
        float vB00 = tanhf(cB00 + xB00.x), vB01 = tanhf(cB01 + xB00.y);
        float vB02 = tanhf(cB02 + xB01.x), vB03 = tanhf(cB03 + xB01.y);
        float vB10 = tanhf(cB10 + xB10.x), vB11 = tanhf(cB11 + xB10.y);
        float vB12 = tanhf(cB12 + xB11.x), vB13 = tanhf(cB13 + xB11.y);

        if (t == Tsz - 1) {   // full-precision final h for the FC
            float* hfA = g_hfin + jcA;
            float* hfB = g_hfin + jcB;
            *reinterpret_cast<float2*>(hfA + (size_t)(r0     ) * Hsz) = make_float2(vA00, vA01);
            *reinterpret_cast<float2*>(hfA + (size_t)(r0 +  8) * Hsz) = make_float2(vA02, vA03);
            *reinterpret_cast<float2*>(hfA + (size_t)(r0 + 16) * Hsz) = make_float2(vA10, vA11);
            *reinterpret_cast<float2*>(hfA + (size_t)(r0 + 24) * Hsz) = make_float2(vA12, vA13);
            *reinterpret_cast<float2*>(hfB + (size_t)(r0     ) * Hsz) = make_float2(vB00, vB01);
            *reinterpret_cast<float2*>(hfB + (size_t)(r0 +  8) * Hsz) = make_float2(vB02, vB03);
            *reinterpret_cast<float2*>(hfB + (size_t)(r0 + 16) * Hsz) = make_float2(vB10, vB11);
            *reinterpret_cast<float2*>(hfB + (size_t)(r0 + 24) * Hsz) = make_float2(vB12, vB13);
        }

        // ---- C-layout -> A-layout transpose (per-warp staging), store frags ----
        // stg[warp]: [i(2)][mt(2)][row16][col8] u32
        stg[wo +   0 + 0   + gid * 8 + 2*tig    ] = f2tf32(vA00);
        stg[wo +   0 + 0   + gid * 8 + 2*tig + 1] = f2tf32(vA01);
        stg[wo +   0 + 0   + (gid + 8) * 8 + 2*tig    ] = f2tf32(vA02);
        stg[wo +   0 + 0   + (gid + 8) * 8 + 2*tig + 1] = f2tf32(vA03);
        stg[wo +   0 + 128 + gid * 8 + 2*tig    ] = f2tf32(vA10);
        stg[wo +   0 + 128 + gid * 8 + 2*tig + 1] = f2tf32(vA11);
        stg[wo +   0 + 128 + (gid + 8) * 8 + 2*tig    ] = f2tf32(vA12);
        stg[wo +   0 + 128 + (gid + 8) * 8 + 2*tig + 1] = f2tf32(vA13);
        stg[wo + 256 + 0   + gid * 8 + 2*tig    ] = f2tf32(vB00);
        stg[wo + 256 + 0   + gid * 8 + 2*tig + 1] = f2tf32(vB01);
        stg[wo + 256 + 0   + (gid + 8) * 8 + 2*tig    ] = f2tf32(vB02);
        stg[wo + 256 + 0   + (gid + 8) * 8 + 2*tig + 1] = f2tf32(vB03);
        stg[wo + 256 + 128 + gid * 8 + 2*tig    ] = f2tf32(vB10);
        stg[wo + 256 + 128 + gid * 8 + 2*tig + 1] = f2tf32(vB11);
        stg[wo + 256 + 128 + (gid + 8) * 8 + 2*tig    ] = f2tf32(vB12);
        stg[wo + 256 + 128 + (gid + 8) * 8 + 2*tig + 1] = f2tf32(vB13);
        __syncwarp();

        uint4* hw = g_hfrag + ((size_t)((t & 1) ^ 1) * BG + bg) * (NKT * 2 * 32);
        #pragma unroll
        for (int i = 0; i < 2; ++i) {
            const int ktw = jg * 8 + 2 * wid + i;
            #pragma unroll
            for (int mt = 0; mt < 2; ++mt) {
                const int sb = wo + i * 256 + mt * 128;
                uint4 a;
                a.x = stg[sb + gid * 8 + tig];
                a.y = stg[sb + (gid + 8) * 8 + tig];
                a.z = stg[sb + gid * 8 + tig + 4];
                a.w = stg[sb + (gid + 8) * 8 + tig + 4];
                hw[(ktw * 2 + mt) * 32 + lane] = a;
            }
        }

        // ---- Release ----
        __threadfence();
        __syncthreads();
        if (tid == 0) atomicAdd(&g_cnt[bg], 1u);
    }
}

// out[b] = fc_b + sum_j fc_w[j] * h_final[b][j]
__global__ void rnn_fc_kernel(const float* __restrict__ fcw,
                              const float* __restrict__ fcb,
                              float* __restrict__ out)
{
    int b    = blockIdx.x;       // 0..255
    int lane = threadIdx.x;      // 32 threads
    const float* hb = g_hfin + (size_t)b * Hsz;
    float s = 0.f;
    #pragma unroll 4
    for (int j = lane; j < Hsz; j += 32)
        s += fcw[j] * hb[j];
    #pragma unroll
    for (int o = 16; o; o >>= 1) s += __shfl_down_sync(0xffffffffu, s, o);
    if (lane == 0) out[b] = s + fcb[0];
}

extern "C" void kernel_launch(void* const* d_in, const int* in_sizes, int n_in,
                              void* d_out, int out_size)
{
    const float* x    = (const float*)d_in[0];   // (256, 512, 64)
    const float* Wxh  = (const float*)d_in[1];   // (64, 512)
    const float* Whh  = (const float*)d_in[2];   // (512, 512)
    const float* bias = (const float*)d_in[3];   // (512,)
    const float* fcw  = (const float*)d_in[4];   // (1, 512)
    const float* fcb  = (const float*)d_in[5];   // (1,)
    float* out = (float*)d_out;                  // (256, 1) fp32

    cudaFuncSetAttribute(rnn_persist_kernel,
                         cudaFuncAttributeMaxDynamicSharedMemorySize, SMEM_BYTES);

    wlin_setup_kernel<<<512, 256>>>(Whh);
    cnt_init_kernel<<<1, 32>>>();
    dim3 pre_grid(Bsz * Tsz / 16, JG);           // 8192 x 8
    xh_precompute_kernel<<<pre_grid, 128>>>(x, Wxh, bias);

    rnn_persist_kernel<<<NCTA, NTHR, SMEM_BYTES>>>();

    rnn_fc_kernel<<<Bsz, 32>>>(fcw, fcb, out);
}

// round 16
// speedup vs baseline: 2.2900x; 1.0367x over previous
#include <cuda_runtime.h>
#include <math.h>

// Problem dims (fixed by the reference)
#define Bsz 256
#define Tsz 512
#define Isz 64
#define Hsz 512

// 8 batch-groups (32 rows: two 16-row streams) x 8 hout-groups (64 cols)
#define BG 8
#define JG 8
#define NCTA (BG*JG)   // 64 CTAs, 1/SM, all wave-1 resident
#define NTHR 128       // warps 0-1 = stream 0, warps 2-3 = stream 1

#define NKT (Hsz/8)    // 64 k-tiles

// SMEM layout
#define WSM_U4   8192                         // W slice [nt(8)][kt(64)][lane] uint2 = 128 KB
#define HD_U4    (NKT*32)                     // per-stream h A-frags = 32 KB
#define SMEM_BYTES (WSM_U4*16 + 2*HD_U4*16 + 4*512*4)   // 204,800 B

// ---- Global scratch ----
__device__ float    g_xh[(size_t)Bsz * Tsz * Hsz];     // x@Wxh + bias, [b*T+t][H]
__device__ unsigned g_w[64 * 64 * 32 * 2];             // W_hh B-frag order (tf32)
// h A-frags: [buf(2)][stream(2)][bg(8)][kt(64)][lane(32)] uint4, double buffered
__device__ uint4    g_hfrag[2 * 2 * BG * NKT * 32];
__device__ float    g_hfin[Bsz * Hsz];                 // fp32 final h
__device__ unsigned g_cnt[16];                         // [stream*8 + bg]

// ---- helpers ----
__device__ __forceinline__ void cp16(void* smem_dst, const void* gsrc) {
    unsigned d = (unsigned)__cvta_generic_to_shared(smem_dst);
    asm volatile("cp.async.cg.shared.global [%0], [%1], 16;" :: "r"(d), "l"(gsrc));
}
#define CP_COMMIT() asm volatile("cp.async.commit_group;")
#define CP_WAIT(n)  asm volatile("cp.async.wait_group %0;" :: "n"(n))
#define GBAR(id)    asm volatile("bar.sync %0, 64;" :: "r"(id) : "memory")

__device__ __forceinline__ unsigned f2tf32(float f) {
    unsigned r;
    asm("cvt.rna.tf32.f32 %0, %1;" : "=r"(r) : "f"(f));
    return r;
}
__device__ __forceinline__ void mma_tf32(float& d0, float& d1, float& d2, float& d3,
                                         uint4 a, uint2 b) {
    asm volatile(
        "mma.sync.aligned.m16n8k8.row.col.f32.tf32.tf32.f32 "
        "{%0,%1,%2,%3}, {%4,%5,%6,%7}, {%8,%9}, {%0,%1,%2,%3};"
        : "+f"(d0), "+f"(d1), "+f"(d2), "+f"(d3)
        : "r"(a.x), "r"(a.y), "r"(a.z), "r"(a.w), "r"(b.x), "r"(b.y));
}
__device__ __forceinline__ void ffma2(unsigned long long& d,
                                      unsigned long long a, unsigned long long b) {
    asm("fma.rn.f32x2 %0, %1, %2, %0;" : "+l"(d) : "l"(a), "l"(b));
}
__device__ __forceinline__ unsigned long long packf2(float lo, float hi) {
    unsigned long long r;
    asm("mov.b64 %0, {%1, %2};" : "=l"(r) : "f"(lo), "f"(hi));
    return r;
}
__device__ __forceinline__ float2 unpackf2(unsigned long long v) {
    float2 r;
    asm("mov.b64 {%0, %1}, %2;" : "=f"(r.x), "=f"(r.y) : "l"(v));
    return r;
}

// ---------------------------------------------------------------------------
// One-time: W_hh -> B-fragment order (tf32). [nt(64)][kt(64)][lane][2]
// ---------------------------------------------------------------------------
__global__ void wlin_setup_kernel(const float* __restrict__ Whh) {
    int idx = blockIdx.x * 256 + threadIdx.x;      // nt*2048 + kt*32 + lane
    int nt   = idx >> 11;
    int kt   = (idx >> 5) & 63;
    int lane = idx & 31;
    int gid  = lane >> 2, tig = lane & 3;
    int col  = nt * 8 + gid;
    g_w[idx * 2 + 0] = f2tf32(Whh[(size_t)(kt * 8 + tig)     * Hsz + col]);
    g_w[idx * 2 + 1] = f2tf32(Whh[(size_t)(kt * 8 + tig + 4) * Hsz + col]);
}

__global__ void cnt_init_kernel() {
    if (threadIdx.x < 16) g_cnt[threadIdx.x] = 0u;
}

// ---------------------------------------------------------------------------
// Precompute xh[r][h] = bias[h] + sum_i x[r][i]*Wxh[i][h]   (r = b*T + t)
// ---------------------------------------------------------------------------
#define PXD_OFF  (Isz*64)
__global__ void __launch_bounds__(128)
xh_precompute_kernel(const float* __restrict__ x,
                     const float* __restrict__ Wxh,
                     const float* __restrict__ bias)
{
    __shared__ float sm[PXD_OFF + Isz*18*2];
    float*  Wxs = sm;
    float2* xd  = reinterpret_cast<float2*>(sm + PXD_OFF);

    const int tid  = threadIdx.x;
    const int rt   = blockIdx.x;
    const int jg   = blockIdx.y;
    const int lane = tid & 31;
    const int wq   = tid >> 5;
    const int b0   = wq * 4;
    const int j0   = lane * 2;
    const int r0   = rt * 16;

    #pragma unroll
    for (int m = 0; m < 8; ++m) {
        int idx = m * 128 + tid;
        int k  = idx >> 4;
        int f  = idx & 15;
        *reinterpret_cast<float4*>(Wxs + k * 64 + f * 4) =
            *reinterpret_cast<const float4*>(Wxh + (size_t)k * Hsz + jg * 64 + f * 4);
    }
    #pragma unroll
    for (int m = 0; m < 2; ++m) {
        int idx = m * 128 + tid;
        int bb  = idx & 15;
        int f   = idx >> 4;
        float4 v = *reinterpret_cast<const float4*>(x + (size_t)(r0 + bb) * Isz + f * 4);
        xd[(f * 4 + 0) * 18 + bb] = make_float2(v.x, v.x);
        xd[(f * 4 + 1) * 18 + bb] = make_float2(v.y, v.y);
        xd[(f * 4 + 2) * 18 + bb] = make_float2(v.z, v.z);
        xd[(f * 4 + 3) * 18 + bb] = make_float2(v.w, v.w);
    }
    const unsigned long long biasPair =
        packf2(bias[jg * 64 + j0], bias[jg * 64 + j0 + 1]);
    __syncthreads();

    unsigned long long acc0 = biasPair, acc1 = biasPair,
                       acc2 = biasPair, acc3 = biasPair;
    #pragma unroll 4
    for (int k = 0; k < Isz; ++k) {
        ulonglong2 xA = *reinterpret_cast<const ulonglong2*>(xd + (k * 18 + b0));
        ulonglong2 xB = *reinterpret_cast<const ulonglong2*>(xd + (k * 18 + b0 + 2));
        unsigned long long wv =
            *reinterpret_cast<const unsigned long long*>(Wxs + k * 64 + j0);
        ffma2(acc0, xA.x, wv); ffma2(acc1, xA.y, wv);
        ffma2(acc2, xB.x, wv); ffma2(acc3, xB.y, wv);
    }

    float* outp = g_xh + (size_t)(r0 + b0) * Hsz + jg * 64 + j0;
    *reinterpret_cast<float2*>(outp + 0 * Hsz) = unpackf2(acc0);
    *reinterpret_cast<float2*>(outp + 1 * Hsz) = unpackf2(acc1);
    *reinterpret_cast<float2*>(outp + 2 * Hsz) = unpackf2(acc2);
    *reinterpret_cast<float2*>(outp + 3 * Hsz) = unpackf2(acc3);
}

// ---------------------------------------------------------------------------
// Persistent recurrence, warp-specialized dual-stream.
// Stream s (warps 2s, 2s+1) owns rows bg*32 + s*16 .. +15 (one m-tile).
// Warp covers 4 n-tiles: nt_local = (wid&1)*4 + q.
// ---------------------------------------------------------------------------
__global__ void __launch_bounds__(NTHR, 1)
rnn_persist_kernel()
{
    extern __shared__ unsigned smu[];
    uint2*    wsm = reinterpret_cast<uint2*>(smu);                    // [nt8][kt64][lane]
    uint4*    hd  = reinterpret_cast<uint4*>(smu + WSM_U4*4);         // 2 x [kt64][lane]
    unsigned* stg = smu + WSM_U4*4 + 2*HD_U4*4;                       // [warp][512]

    const int tid  = threadIdx.x;
    const int wid  = tid >> 5;          // 0..3
    const int lane = tid & 31;
    const int gid  = lane >> 2;
    const int tig  = lane & 3;
    const int s    = wid >> 1;          // stream 0/1
    const int wi   = wid & 1;           // warp-in-stream
    const int gt   = tid & 63;          // thread index within stream group
    const int bg   = blockIdx.x >> 3;
    const int jg   = blockIdx.x & 7;
    const int barid = 1 + s;

    // ---- One-time: W slice for this jg (contiguous 128 KB) -> SMEM ----
    {
        const uint4* wg = reinterpret_cast<const uint4*>(g_w) + (size_t)jg * WSM_U4;
        #pragma unroll 8
        for (int m = 0; m < WSM_U4 / NTHR; ++m)                       // 64 iters
            reinterpret_cast<uint4*>(wsm)[m * NTHR + tid] = wg[m * NTHR + tid];
    }
    __syncthreads();

    const int   r0  = bg * 32 + s * 16 + gid;     // rows r0, r0+8
    const size_t TH = (size_t)Tsz * Hsz;
    uint4* hd_s = hd + s * HD_U4;
    const int wo = wid * 512;
    unsigned* cnt = &g_cnt[s * 8 + bg];
    // columns for q=0..3: jc[q] = jg*64 + (wi*4+q)*8 + 2*tig
    const int jcb = jg * 64 + wi * 32 + 2 * tig;

    for (int t = 0; t < Tsz; ++t) {
        // ---- xh prefetch (independent of h) ----
        float2 xh0[4], xh1[4];
        #pragma unroll
        for (int q = 0; q < 4; ++q) {
            const float* xb = g_xh + (size_t)t * Hsz + jcb + q * 8;
            xh0[q] = __ldg(reinterpret_cast<const float2*>(xb + (size_t)r0 * TH));
            xh1[q] = __ldg(reinterpret_cast<const float2*>(xb + (size_t)(r0 + 8) * TH));
        }

        float acc[4][4];
        #pragma unroll
        for (int q = 0; q < 4; ++q)
            acc[q][0] = acc[q][1] = acc[q][2] = acc[q][3] = 0.f;

        if (t > 0) {
            // ---- Acquire (per stream): all 8 producers done with t-1 ----
            if (wi == 0 && lane == 0) {
                volatile unsigned* c = cnt;
                const unsigned target = 8u * (unsigned)t;
                while (*c < target) { __nanosleep(32); }
                __threadfence();
            }
            GBAR(barid);

            // ---- Stage this stream's h A-frags (32 KB) in 2 cp.async chunks ----
            const uint4* hg = g_hfrag
                + ((size_t)((t & 1) * 2 + s) * BG + bg) * HD_U4;
            #pragma unroll
            for (int c = 0; c < 2; ++c) {
                #pragma unroll
                for (int m = 0; m < 16; ++m) {
                    int idx = c * 1024 + m * 64 + gt;
                    cp16(hd_s + idx, hg + idx);
                }
                CP_COMMIT();
            }

            // ---- MMA, chunk-pipelined ----
            #pragma unroll
            for (int c = 0; c < 2; ++c) {
                if (c == 0) { CP_WAIT(1); } else { CP_WAIT(0); }
                GBAR(barid);
                #pragma unroll 8
                for (int kt = c * 32; kt < c * 32 + 32; ++kt) {
                    uint4 a = hd_s[kt * 32 + lane];
                    #pragma unroll
                    for (int q = 0; q < 4; ++q) {
                        uint2 b = wsm[((wi * 4 + q) * NKT + kt) * 32 + lane];
                        mma_tf32(acc[q][0], acc[q][1], acc[q][2], acc[q][3], a, b);
                    }
                }
            }
        }

        // ---- Epilogue: add xh, tanh; stage transpose; store A-frags ----
        uint4* hw = g_hfrag
            + ((size_t)(((t & 1) ^ 1) * 2 + s) * BG + bg) * HD_U4;

        #pragma unroll
        for (int q = 0; q < 4; ++q) {
            float v0 = tanhf(acc[q][0] + xh0[q].x);
            float v1 = tanhf(acc[q][1] + xh0[q].y);
            float v2 = tanhf(acc[q][2] + xh1[q].x);
            float v3 = tanhf(acc[q][3] + xh1[q].y);

            if (t == Tsz - 1) {
                float* hf = g_hfin + jcb + q * 8;
                *reinterpret_cast<float2*>(hf + (size_t)r0 * Hsz)       = make_float2(v0, v1);
                *reinterpret_cast<float2*>(hf + (size_t)(r0 + 8) * Hsz) = make_float2(v2, v3);
            }
            const int sb = wo + q * 128;
            stg[sb + gid * 8 + 2 * tig    ] = f2tf32(v0);
            stg[sb + gid * 8 + 2 * tig + 1] = f2tf32(v1);
            stg[sb + (gid + 8) * 8 + 2 * tig    ] = f2tf32(v2);
            stg[sb + (gid + 8) * 8 + 2 * tig + 1] = f2tf32(v3);
        }
        __syncwarp();
        #pragma unroll
        for (int q = 0; q < 4; ++q) {
            const int sb  = wo + q * 128;
            const int ktw = jg * 8 + wi * 4 + q;
            uint4 a;
            a.x = stg[sb + gid * 8 + tig];
            a.y = stg[sb + (gid + 8) * 8 + tig];
            a.z = stg[sb + gid * 8 + tig + 4];
            a.w = stg[sb + (gid + 8) * 8 + tig + 4];
            hw[ktw * 32 + lane] = a;
        }

        // ---- Release (per stream) ----
        __threadfence();
        GBAR(barid);
        if (wi == 0 && lane == 0) atomicAdd(cnt, 1u);
    }
}

// out[b] = fc_b + sum_j fc_w[j] * h_final[b][j]
__global__ void rnn_fc_kernel(const float* __restrict__ fcw,
                              const float* __restrict__ fcb,
                              float* __restrict__ out)
{
    int b    = blockIdx.x;       // 0..255
    int lane = threadIdx.x;      // 32 threads
    const float* hb = g_hfin + (size_t)b * Hsz;
    float ssum = 0.f;
    #pragma unroll 4
    for (int j = lane; j < Hsz; j += 32)
        ssum += fcw[j] * hb[j];
    #pragma unroll
    for (int o = 16; o; o >>= 1) ssum += __shfl_down_sync(0xffffffffu, ssum, o);
    if (lane == 0) out[b] = ssum + fcb[0];
}

extern "C" void kernel_launch(void* const* d_in, const int* in_sizes, int n_in,
                              void* d_out, int out_size)
{
    const float* x    = (const float*)d_in[0];   // (256, 512, 64)
    const float* Wxh  = (const float*)d_in[1];   // (64, 512)
    const float* Whh  = (const float*)d_in[2];   // (512, 512)
    const float* bias = (const float*)d_in[3];   // (512,)
    const float* fcw  = (const float*)d_in[4];   // (1, 512)
    const float* fcb  = (const float*)d_in[5];   // (1,)
    float* out = (float*)d_out;                  // (256, 1) fp32

    cudaFuncSetAttribute(rnn_persist_kernel,
                         cudaFuncAttributeMaxDynamicSharedMemorySize, SMEM_BYTES);

    wlin_setup_kernel<<<512, 256>>>(Whh);
    cnt_init_kernel<<<1, 32>>>();
    dim3 pre_grid(Bsz * Tsz / 16, JG);           // 8192 x 8
    xh_precompute_kernel<<<pre_grid, 128>>>(x, Wxh, bias);

    rnn_persist_kernel<<<NCTA, NTHR, SMEM_BYTES>>>();

    rnn_fc_kernel<<<Bsz, 32>>>(fcw, fcb, out);
}